// round 9
// baseline (speedup 1.0000x reference)
#include <cuda_runtime.h>
#include <cuda_bf16.h>
#include <cuda_fp16.h>
#include <cuda_fp8.h>
#include <cstdint>
#include <math.h>

#define BATCH 4
#define CH    512
#define HW    4096
#define NGRP  32
#define CPG   16

static const size_t CHW  = (size_t)CH * HW;
static const size_t QKW  = (size_t)HW * 1024;
static const size_t SHW  = (size_t)HW * HW;
#define CC (CH * CH)

// ---------------- scratch ----------------
__device__ __nv_bfloat16 g_xn [BATCH * CH * HW];   // [c, hw] bf16
__device__ __nv_bfloat16 g_xnT[BATCH * CH * HW];   // [hw, c] bf16
__device__ uint8_t       g_qk [BATCH * HW * 1024]; // [hw, q|k] fp8
__device__ uint8_t       g_v  [BATCH * CH * HW];   // [c, hw] fp8
__device__ uint8_t       g_s  [BATCH * HW * HW];   // fp8 scores
__device__ uint8_t       g_at [BATCH * HW * HW];   // fp8 attn*256
__device__ __nv_bfloat16 g_o2 [BATCH * CH * HW];   // [hw, c] bf16
__device__ __nv_bfloat16 g_w  [4 * CH * CH];       // wq, wk, wv, wp bf16
__device__ float         g_bqk[1024];

// ---------------- PTX helpers ----------------
__device__ __forceinline__ uint32_t smem_u32(const void* p) {
    uint32_t a;
    asm("{ .reg .u64 t; cvta.to.shared.u64 t, %1; cvt.u32.u64 %0, t; }"
        : "=r"(a) : "l"(p));
    return a;
}
__device__ __forceinline__ void cp16(uint32_t s, const void* g) {
    asm volatile("cp.async.cg.shared.global [%0], [%1], 16;"
                 :: "r"(s), "l"(__cvta_generic_to_global(g)) : "memory");
}
#define CP_COMMIT() asm volatile("cp.async.commit_group;" ::: "memory")
#define CP_WAIT1()  asm volatile("cp.async.wait_group 1;"  ::: "memory")

__device__ __forceinline__ void ldsm_x4(uint32_t* r, uint32_t addr) {
    asm volatile("ldmatrix.sync.aligned.m8n8.x4.shared.b16 {%0,%1,%2,%3}, [%4];"
        : "=r"(r[0]), "=r"(r[1]), "=r"(r[2]), "=r"(r[3]) : "r"(addr));
}
__device__ __forceinline__ void mma16816(float* c, const uint32_t* a,
                                         uint32_t b0, uint32_t b1) {
    asm volatile(
        "mma.sync.aligned.m16n8k16.row.col.f32.bf16.bf16.f32 "
        "{%0,%1,%2,%3}, {%4,%5,%6,%7}, {%8,%9}, {%0,%1,%2,%3};"
        : "+f"(c[0]), "+f"(c[1]), "+f"(c[2]), "+f"(c[3])
        : "r"(a[0]), "r"(a[1]), "r"(a[2]), "r"(a[3]), "r"(b0), "r"(b1));
}
__device__ __forceinline__ void mma_f8h(uint32_t* c, const uint32_t* a,
                                        uint32_t b0, uint32_t b1) {
    asm volatile(
        "mma.sync.aligned.m16n8k32.row.col.f16.e4m3.e4m3.f16 "
        "{%0,%1}, {%2,%3,%4,%5}, {%6,%7}, {%0,%1};"
        : "+r"(c[0]), "+r"(c[1])
        : "r"(a[0]), "r"(a[1]), "r"(a[2]), "r"(a[3]), "r"(b0), "r"(b1));
}
__device__ __forceinline__ uint16_t f2_to_e4m3x2(float x0, float x1) {
    return (uint16_t)__nv_cvt_float2_to_fp8x2(make_float2(x0, x1),
                                              __NV_SATFINITE, __NV_E4M3);
}
__device__ __forceinline__ float2 e4m3x2_to_f2(uint16_t h) {
    __half2_raw hr = __nv_cvt_fp8x2_to_halfraw2((__nv_fp8x2_storage_t)h, __NV_E4M3);
    return __half22float2(*reinterpret_cast<__half2*>(&hr));
}

// ---------------------------------------------------------------------------
// GroupNorm -> bf16 [c, hw]
// ---------------------------------------------------------------------------
__global__ __launch_bounds__(256) void groupnorm_kernel(
    const float* __restrict__ x, const float* __restrict__ scale,
    const float* __restrict__ bias, __nv_bfloat16* __restrict__ xn)
{
    const int b = blockIdx.x / NGRP, g = blockIdx.x % NGRP;
    const size_t base = ((size_t)b * CH + (size_t)g * CPG) * HW;
    const int n4 = CPG * HW / 4;

    const float4* xin = reinterpret_cast<const float4*>(x + base);
    float s = 0.f, ss = 0.f;
    for (int i = threadIdx.x; i < n4; i += 256) {
        float4 t = xin[i];
        s  += t.x + t.y + t.z + t.w;
        ss += t.x * t.x + t.y * t.y + t.z * t.z + t.w * t.w;
    }
    __shared__ float r1[256], r2[256];
    r1[threadIdx.x] = s; r2[threadIdx.x] = ss;
    __syncthreads();
    for (int off = 128; off > 0; off >>= 1) {
        if (threadIdx.x < off) {
            r1[threadIdx.x] += r1[threadIdx.x + off];
            r2[threadIdx.x] += r2[threadIdx.x + off];
        }
        __syncthreads();
    }
    const float inv_n = 1.f / (float)(CPG * HW);
    const float mean = r1[0] * inv_n;
    const float var  = fmaxf(r2[0] * inv_n - mean * mean, 0.f);
    const float rstd = rsqrtf(var + 1e-6f);

    uint2* xo = reinterpret_cast<uint2*>(xn + base);
    for (int i = threadIdx.x; i < n4; i += 256) {
        const int c = g * CPG + (i >> 10);
        const float a = scale[c] * rstd;
        const float d = bias[c] - mean * a;
        float4 t = xin[i];
        __nv_bfloat162 h0 = __floats2bfloat162_rn(t.x * a + d, t.y * a + d);
        __nv_bfloat162 h1 = __floats2bfloat162_rn(t.z * a + d, t.w * a + d);
        uint2 o;
        o.x = *reinterpret_cast<uint32_t*>(&h0);
        o.y = *reinterpret_cast<uint32_t*>(&h1);
        xo[i] = o;
    }
}

// ---------------------------------------------------------------------------
// 16-bit transpose [R, C] -> [C, R]
// ---------------------------------------------------------------------------
__global__ __launch_bounds__(256) void transpose_h16(
    const uint16_t* __restrict__ in, uint16_t* __restrict__ out, int R, int C)
{
    __shared__ uint16_t tile[64][72];
    const size_t zoff = (size_t)blockIdx.z * (size_t)R * C;
    const int r0 = blockIdx.y * 64, c0 = blockIdx.x * 64;

    #pragma unroll
    for (int it = 0; it < 2; it++) {
        int idx = threadIdx.x + it * 256;
        int r = idx >> 3, c8 = idx & 7;
        uint4 v = *reinterpret_cast<const uint4*>(in + zoff + (size_t)(r0 + r) * C + c0 + c8 * 8);
        *reinterpret_cast<uint4*>(&tile[r][c8 * 8]) = v;
    }
    __syncthreads();
    #pragma unroll
    for (int it = 0; it < 2; it++) {
        int idx = threadIdx.x + it * 256;
        int c = idx >> 3, r8 = idx & 7;
        uint16_t tmp[8];
        #pragma unroll
        for (int i = 0; i < 8; i++) tmp[i] = tile[r8 * 8 + i][c];
        *reinterpret_cast<uint4*>(out + zoff + (size_t)(c0 + c) * R + r0 + r8 * 8) =
            *reinterpret_cast<uint4*>(tmp);
    }
}

// ---------------------------------------------------------------------------
// weights fp32 -> bf16 (+ concat bias)
// ---------------------------------------------------------------------------
__global__ __launch_bounds__(256) void cvt_w_kernel(
    const float* __restrict__ a, const float* __restrict__ b,
    const float* __restrict__ c, const float* __restrict__ d,
    const float* __restrict__ bq, const float* __restrict__ bk,
    __nv_bfloat16* __restrict__ w, float* __restrict__ bqk)
{
    const int i = blockIdx.x * 256 + threadIdx.x;
    const float* s = (blockIdx.y == 0) ? a : (blockIdx.y == 1) ? b : (blockIdx.y == 2) ? c : d;
    w[(size_t)blockIdx.y * CC + i] = __float2bfloat16(s[i]);
    if (blockIdx.y == 0 && i < 1024)
        bqk[i] = (i < 512) ? bq[i] : bk[i - 512];
}

// ---------------------------------------------------------------------------
// bf16 GEMM (QKV + proj): 128x128 tile, 8 warps 4Mx2N (32x64), 3 stages.
// ---------------------------------------------------------------------------
#define PITCH  144
#define OPSZ   18432
#define STG_SZ 36864
#define SMEM_TC 110592

template<int OT>   // 0 = fp32 out, 2 = fp8 out
__global__ void __launch_bounds__(256, 2) gemm_tc(
    const __nv_bfloat16* __restrict__ Ag, const __nv_bfloat16* __restrict__ Bg,
    void* __restrict__ Cout,
    const float* __restrict__ bias_m, const float* __restrict__ bias_n,
    int M, int N, int K, int lda, int ldb,
    float alpha, float addc,
    size_t sA, size_t sB, size_t sC)
{
    extern __shared__ __align__(16) char smem[];
    const uint32_t sb = smem_u32(smem);

    const int tid  = threadIdx.x;
    const int lane = tid & 31;
    const int wid  = tid >> 5;
    const int wm   = wid >> 1;
    const int wn   = wid & 1;
    const int bm = blockIdx.y * 128;
    const int bn = blockIdx.x * 128;

    const uint8_t* Ab = (const uint8_t*)(Ag + (size_t)blockIdx.z * sA + (size_t)bm * lda);
    const uint8_t* Bb = (const uint8_t*)(Bg + (size_t)blockIdx.z * sB + (size_t)bn * ldb);

    int rr[4];
    uint32_t so[4], go[4];
    #pragma unroll
    for (int j = 0; j < 4; j++) {
        const int idx = tid + j * 256;
        rr[j] = idx >> 3;
        const int cc = idx & 7;
        so[j] = (uint32_t)rr[j] * PITCH + cc * 16;
        go[j] = cc * 16;
    }

    const int nk = K >> 6;

    #pragma unroll
    for (int s = 0; s < 2; s++) {
        const uint32_t kb = (uint32_t)s * 128;
        const uint32_t st = sb + s * STG_SZ;
        #pragma unroll
        for (int j = 0; j < 4; j++) {
            cp16(st + so[j],        Ab + (size_t)rr[j] * lda * 2 + kb + go[j]);
            cp16(st + OPSZ + so[j], Bb + (size_t)rr[j] * ldb * 2 + kb + go[j]);
        }
        CP_COMMIT();
    }

    float acc[2][8][4];
    #pragma unroll
    for (int i = 0; i < 2; i++)
        #pragma unroll
        for (int j = 0; j < 8; j++)
            #pragma unroll
            for (int t = 0; t < 4; t++) acc[i][j][t] = 0.f;

    const uint32_t lrow = lane & 15;
    const uint32_t lsel = (lane >> 4) * 16;

    int buf = 0;
    for (int ck = 0; ck < nk; ck++) {
        CP_WAIT1();
        __syncthreads();

        if (ck + 2 < nk) {
            const uint32_t kb = (uint32_t)(ck + 2) * 128;
            const uint32_t st = sb + ((buf + 2) % 3) * STG_SZ;
            #pragma unroll
            for (int j = 0; j < 4; j++) {
                cp16(st + so[j],        Ab + (size_t)rr[j] * lda * 2 + kb + go[j]);
                cp16(st + OPSZ + so[j], Bb + (size_t)rr[j] * ldb * 2 + kb + go[j]);
            }
        }
        CP_COMMIT();

        const uint32_t sa  = sb + buf * STG_SZ;
        const uint32_t sbm = sa + OPSZ;
        #pragma unroll
        for (int kf = 0; kf < 4; kf++) {
            const uint32_t kofs = kf * 32 + lsel;
            uint32_t ar[2][4];
            #pragma unroll
            for (int mi = 0; mi < 2; mi++)
                ldsm_x4(ar[mi], sa + (wm * 32 + mi * 16 + lrow) * PITCH + kofs);
            uint32_t br[4][4];
            #pragma unroll
            for (int nb = 0; nb < 4; nb++)
                ldsm_x4(br[nb], sbm + (wn * 64 + nb * 16 + lrow) * PITCH + kofs);
            #pragma unroll
            for (int mi = 0; mi < 2; mi++)
                #pragma unroll
                for (int nj = 0; nj < 8; nj++) {
                    const int nb = nj >> 1, od = nj & 1;
                    mma16816(acc[mi][nj], ar[mi], br[nb][od], br[nb][od + 2]);
                }
        }
        buf = (buf + 1) % 3;
    }

    const int gid = lane >> 2, tig = lane & 3;
    #pragma unroll
    for (int mi = 0; mi < 2; mi++) {
        #pragma unroll
        for (int r2 = 0; r2 < 2; r2++) {
            const int m = bm + wm * 32 + mi * 16 + gid + r2 * 8;
            const float bmv = (bias_m ? bias_m[m] : 0.f) + addc;
            #pragma unroll
            for (int nj = 0; nj < 8; nj++) {
                const int n = bn + wn * 64 + nj * 8 + tig * 2;
                float x0 = acc[mi][nj][r2 * 2]     * alpha + bmv;
                float x1 = acc[mi][nj][r2 * 2 + 1] * alpha + bmv;
                if (bias_n) { x0 += bias_n[n]; x1 += bias_n[n + 1]; }
                const size_t off = (size_t)blockIdx.z * sC + (size_t)m * N + n;
                if (OT == 0) {
                    *reinterpret_cast<float2*>((float*)Cout + off) = make_float2(x0, x1);
                } else {
                    *reinterpret_cast<uint16_t*>((uint8_t*)Cout + off)
                        = f2_to_e4m3x2(x0, x1);
                }
            }
        }
    }
}

// ---------------------------------------------------------------------------
// fp8 attention GEMM, f16 acc: D[M,N] = alpha * A[M,K] @ B[N,K]^T
// 256x128 block tile, 8 warps (4Mx2N of 64x64), 256 threads.
// K-chunk = 64 fp8 (64 B rows, pitch 80), 3-stage cp.async.
// OT: 1 = bf16 out, 2 = fp8 out.
// ---------------------------------------------------------------------------
#define F8_PITCH  80
#define F8_AOP    20480          // 256 * 80
#define F8_BOP    10240          // 128 * 80
#define F8_STG    30720          // A + B per stage
#define SMEM_F8   92160          // 3 * F8_STG

template<int OT>
__global__ void __launch_bounds__(256, 2) gemm_f8(
    const uint8_t* __restrict__ A, const uint8_t* __restrict__ B,
    void* __restrict__ C,
    int M, int N, int K, int lda, int ldb, float alpha,
    size_t sA, size_t sB, size_t sC)
{
    extern __shared__ __align__(16) char smem[];
    const uint32_t sb = smem_u32(smem);

    const int tid  = threadIdx.x;
    const int lane = tid & 31;
    const int wid  = tid >> 5;
    const int wm   = wid >> 1;       // 0..3  (M, 64 each)
    const int wn   = wid & 1;        // 0..1  (N, 64 each)
    const int bm = blockIdx.y * 256;
    const int bn = blockIdx.x * 128;

    const uint8_t* Ab = A + (size_t)blockIdx.z * sA + (size_t)bm * lda;
    const uint8_t* Bb = B + (size_t)blockIdx.z * sB + (size_t)bn * ldb;

    // cp.async slots: A 4/thread (256 rows x 4 chunks), B 2/thread
    uint32_t soA[4], gA[4], soB[2], gB[2];
    #pragma unroll
    for (int j = 0; j < 4; j++) {
        const int idx = tid + j * 256;          // 0..1023
        const int row = idx >> 2, cc = idx & 3;
        soA[j] = (uint32_t)row * F8_PITCH + cc * 16;
        gA[j]  = (uint32_t)row * lda + cc * 16;
    }
    #pragma unroll
    for (int j = 0; j < 2; j++) {
        const int idx = tid + j * 256;          // 0..511
        const int row = idx >> 2, cc = idx & 3;
        soB[j] = (uint32_t)row * F8_PITCH + cc * 16;
        gB[j]  = (uint32_t)row * ldb + cc * 16;
    }

    const int nk = K >> 6;    // 64 fp8 per chunk

    #pragma unroll
    for (int s = 0; s < 2; s++) {
        const uint32_t kb = (uint32_t)s * 64;
        const uint32_t st = sb + s * F8_STG;
        #pragma unroll
        for (int j = 0; j < 4; j++) cp16(st + soA[j], Ab + gA[j] + kb);
        #pragma unroll
        for (int j = 0; j < 2; j++) cp16(st + F8_AOP + soB[j], Bb + gB[j] + kb);
        CP_COMMIT();
    }

    uint32_t acc[4][8][2];
    #pragma unroll
    for (int i = 0; i < 4; i++)
        #pragma unroll
        for (int j = 0; j < 8; j++) { acc[i][j][0] = 0u; acc[i][j][1] = 0u; }

    const uint32_t lrow = lane & 15;
    const uint32_t lsel = (lane >> 4) * 16;

    int buf = 0;
    for (int ck = 0; ck < nk; ck++) {
        CP_WAIT1();
        __syncthreads();

        if (ck + 2 < nk) {
            const uint32_t kb = (uint32_t)(ck + 2) * 64;
            const uint32_t st = sb + ((buf + 2) % 3) * F8_STG;
            #pragma unroll
            for (int j = 0; j < 4; j++) cp16(st + soA[j], Ab + gA[j] + kb);
            #pragma unroll
            for (int j = 0; j < 2; j++) cp16(st + F8_AOP + soB[j], Bb + gB[j] + kb);
        }
        CP_COMMIT();

        const uint32_t sa  = sb + buf * F8_STG;
        const uint32_t sbm = sa + F8_AOP;
        #pragma unroll
        for (int kf = 0; kf < 2; kf++) {       // 2 x k32 per 64-elem chunk
            const uint32_t kofs = kf * 32 + lsel;
            uint32_t ar[4][4];
            #pragma unroll
            for (int mi = 0; mi < 4; mi++)
                ldsm_x4(ar[mi], sa + (wm * 64 + mi * 16 + lrow) * F8_PITCH + kofs);
            uint32_t br[4][4];
            #pragma unroll
            for (int nb = 0; nb < 4; nb++)
                ldsm_x4(br[nb], sbm + (wn * 64 + nb * 16 + lrow) * F8_PITCH + kofs);
            #pragma unroll
            for (int mi = 0; mi < 4; mi++)
                #pragma unroll
                for (int nj = 0; nj < 8; nj++) {
                    const int nb = nj >> 1, od = nj & 1;
                    mma_f8h(acc[mi][nj], ar[mi], br[nb][od], br[nb][od + 2]);
                }
        }
        buf = (buf + 1) % 3;
    }

    const int gid = lane >> 2, tig = lane & 3;
    #pragma unroll
    for (int mi = 0; mi < 4; mi++) {
        #pragma unroll
        for (int r2 = 0; r2 < 2; r2++) {
            const int m = bm + wm * 64 + mi * 16 + gid + r2 * 8;
            #pragma unroll
            for (int nj = 0; nj < 8; nj++) {
                const int n = bn + wn * 64 + nj * 8 + tig * 2;
                const __half2 h = *reinterpret_cast<const __half2*>(&acc[mi][nj][r2]);
                const float2 f = __half22float2(h);
                const size_t off = (size_t)blockIdx.z * sC + (size_t)m * N + n;
                if (OT == 1) {
                    __nv_bfloat162 ob = __floats2bfloat162_rn(f.x * alpha, f.y * alpha);
                    *reinterpret_cast<uint32_t*>((__nv_bfloat16*)C + off)
                        = *reinterpret_cast<uint32_t*>(&ob);
                } else {
                    *reinterpret_cast<uint16_t*>((uint8_t*)C + off)
                        = f2_to_e4m3x2(f.x * alpha, f.y * alpha);
                }
            }
        }
    }
}

// ---------------------------------------------------------------------------
// Row softmax: fp8 scores in -> fp8 attn*256 out
// ---------------------------------------------------------------------------
__global__ __launch_bounds__(256) void softmax_kernel(
    const uint8_t* __restrict__ s, uint8_t* __restrict__ at)
{
    const uint4* r4 = reinterpret_cast<const uint4*>(s + (size_t)blockIdx.x * HW);
    uint4* o4 = reinterpret_cast<uint4*>(at + (size_t)blockIdx.x * HW);

    uint4 t = r4[threadIdx.x];
    float v[16];
    {
        const uint32_t* u = reinterpret_cast<const uint32_t*>(&t);
        #pragma unroll
        for (int j = 0; j < 4; j++) {
            float2 f0 = e4m3x2_to_f2((uint16_t)(u[j] & 0xFFFF));
            float2 f1 = e4m3x2_to_f2((uint16_t)(u[j] >> 16));
            v[j * 4 + 0] = f0.x; v[j * 4 + 1] = f0.y;
            v[j * 4 + 2] = f1.x; v[j * 4 + 3] = f1.y;
        }
    }
    float mx = -1e30f;
    #pragma unroll
    for (int i = 0; i < 16; i++) mx = fmaxf(mx, v[i]);

    __shared__ float red[256];
    red[threadIdx.x] = mx;
    __syncthreads();
    for (int off = 128; off > 0; off >>= 1) {
        if (threadIdx.x < off)
            red[threadIdx.x] = fmaxf(red[threadIdx.x], red[threadIdx.x + off]);
        __syncthreads();
    }
    mx = red[0];
    __syncthreads();

    float sum = 0.f;
    #pragma unroll
    for (int i = 0; i < 16; i++) { v[i] = __expf(v[i] - mx); sum += v[i]; }
    red[threadIdx.x] = sum;
    __syncthreads();
    for (int off = 128; off > 0; off >>= 1) {
        if (threadIdx.x < off) red[threadIdx.x] += red[threadIdx.x + off];
        __syncthreads();
    }
    const float inv = 256.f / red[0];

    uint4 o;
    uint32_t* u = reinterpret_cast<uint32_t*>(&o);
    #pragma unroll
    for (int j = 0; j < 4; j++) {
        uint32_t lo = f2_to_e4m3x2(v[j * 4 + 0] * inv, v[j * 4 + 1] * inv);
        uint32_t hi = f2_to_e4m3x2(v[j * 4 + 2] * inv, v[j * 4 + 3] * inv);
        u[j] = lo | (hi << 16);
    }
    o4[threadIdx.x] = o;
}

// ---------------------------------------------------------------------------
// Launch
// ---------------------------------------------------------------------------
extern "C" void kernel_launch(void* const* d_in, const int* in_sizes, int n_in,
                              void* d_out, int out_size)
{
    const float* x  = (const float*)d_in[0];
    const float* gs = (const float*)d_in[1];
    const float* gb = (const float*)d_in[2];
    const float* wq = (const float*)d_in[3];
    const float* bq = (const float*)d_in[4];
    const float* wk = (const float*)d_in[5];
    const float* bk = (const float*)d_in[6];
    const float* wv = (const float*)d_in[7];
    const float* bv = (const float*)d_in[8];
    const float* wp = (const float*)d_in[9];
    const float* bp = (const float*)d_in[10];
    float* out = (float*)d_out;

    __nv_bfloat16 *xn, *xnT, *o2, *w;
    uint8_t *qk, *v, *s, *at;
    float *bqk;
    cudaGetSymbolAddress((void**)&xn,  g_xn);
    cudaGetSymbolAddress((void**)&xnT, g_xnT);
    cudaGetSymbolAddress((void**)&qk,  g_qk);
    cudaGetSymbolAddress((void**)&v,   g_v);
    cudaGetSymbolAddress((void**)&s,   g_s);
    cudaGetSymbolAddress((void**)&at,  g_at);
    cudaGetSymbolAddress((void**)&o2,  g_o2);
    cudaGetSymbolAddress((void**)&w,   g_w);
    cudaGetSymbolAddress((void**)&bqk, g_bqk);

    cudaFuncSetAttribute(gemm_tc<2>, cudaFuncAttributeMaxDynamicSharedMemorySize, SMEM_TC);
    cudaFuncSetAttribute(gemm_tc<0>, cudaFuncAttributeMaxDynamicSharedMemorySize, SMEM_TC);
    cudaFuncSetAttribute(gemm_f8<1>, cudaFuncAttributeMaxDynamicSharedMemorySize, SMEM_F8);
    cudaFuncSetAttribute(gemm_f8<2>, cudaFuncAttributeMaxDynamicSharedMemorySize, SMEM_F8);

    // 0) weights -> bf16 (wq|wk contiguous) + concat bias
    cvt_w_kernel<<<dim3(CC / 256, 4), 256>>>(wq, wk, wv, wp, bq, bk, w, bqk);

    // 1) GroupNorm -> bf16 [c, hw]
    groupnorm_kernel<<<BATCH * NGRP, 256>>>(x, gs, gb, xn);

    // 2) transpose xn -> xnT [hw, c]
    transpose_h16<<<dim3(HW / 64, CH / 64, BATCH), 256>>>(
        (const uint16_t*)xn, (uint16_t*)xnT, CH, HW);

    // 3) merged QK -> fp8 [hw, 1024]
    dim3 gQK(1024 / 128, HW / 128, BATCH);
    gemm_tc<2><<<gQK, 256, SMEM_TC>>>(xnT, w, qk, nullptr, bqk,
                                      HW, 1024, CH, CH, CH, 1.f, 0.f, CHW, 0, QKW);

    // 4) V -> fp8 [c, hw]
    dim3 gV(HW / 128, CH / 128, BATCH);
    gemm_tc<2><<<gV, 256, SMEM_TC>>>(w + 2 * CC, xnT, v, bv, nullptr,
                                     CH, HW, CH, CH, CH, 1.f, 0.f, 0, CHW, CHW);

    // 5) scores -> fp8 (A = q cols, B = k cols of merged qk)
    const float alpha = 1.0f / sqrtf((float)CH);
    dim3 gS(HW / 128, HW / 256, BATCH);     // (32, 16, 4)
    gemm_f8<2><<<gS, 256, SMEM_F8>>>(qk, qk + 512, s,
                                     HW, HW, CH, 1024, 1024, alpha, QKW, QKW, SHW);

    // 6) softmax fp8 -> fp8 attn*256
    softmax_kernel<<<BATCH * HW, 256>>>(s, at);

    // 7) o2[hw, c] = attn @ v^T, alpha undoes the 256 scale
    dim3 gO(CH / 128, HW / 256, BATCH);     // (4, 16, 4)
    gemm_f8<1><<<gO, 256, SMEM_F8>>>(at, v, o2,
                                     HW, CH, HW, HW, HW, 1.f / 256.f, SHW, CHW, CHW);

    // 8) proj fp32 + bias + 64
    gemm_tc<0><<<gV, 256, SMEM_TC>>>(w + 3 * CC, o2, out, bp, nullptr,
                                     CH, HW, CH, CH, CH, 1.f, 64.0f, 0, CHW, CHW);
}

// round 10
// speedup vs baseline: 1.0576x; 1.0576x over previous
#include <cuda_runtime.h>
#include <cuda_bf16.h>
#include <cuda_fp16.h>
#include <cuda_fp8.h>
#include <cstdint>
#include <math.h>

#define BATCH 4
#define CH    512
#define HW    4096
#define NGRP  32
#define CPG   16
#define NJT   (HW / 128)        // 32 j-tiles in scores grid

static const size_t CHW = (size_t)CH * HW;
static const size_t SHW = (size_t)HW * HW;
#define CC (CH * CH)

// ---------------- scratch ----------------
__device__ __nv_bfloat16 g_xn  [BATCH * CH * HW];   // [c, hw] bf16
__device__ __nv_bfloat16 g_xnT [BATCH * CH * HW];   // [hw, c] bf16
__device__ uint8_t       g_q   [BATCH * CH * HW];   // [hw, c] fp8
__device__ uint8_t       g_k   [BATCH * CH * HW];   // [hw, c] fp8
__device__ uint8_t       g_v   [BATCH * CH * HW];   // [c, hw] fp8
__device__ uint8_t       g_at  [BATCH * HW * HW];   // fp8 p = exp(alpha*s) (64 MB)
__device__ __nv_bfloat16 g_o2  [BATCH * CH * HW];   // [hw, c] bf16
__device__ __nv_bfloat16 g_w   [4 * CH * CH];       // wq, wk, wv, wp bf16
__device__ float         g_ps  [BATCH * NJT * HW];  // partial row sums (2 MB)
__device__ float         g_rsum[BATCH * HW];        // softmax denominators

// ---------------- PTX helpers (family-portable) ----------------
__device__ __forceinline__ uint32_t smem_u32(const void* p) {
    uint32_t a;
    asm("{ .reg .u64 t; cvta.to.shared.u64 t, %1; cvt.u32.u64 %0, t; }"
        : "=r"(a) : "l"(p));
    return a;
}
__device__ __forceinline__ void cp16(uint32_t s, const void* g) {
    asm volatile("cp.async.cg.shared.global [%0], [%1], 16;"
                 :: "r"(s), "l"(__cvta_generic_to_global(g)) : "memory");
}
#define CP_COMMIT() asm volatile("cp.async.commit_group;" ::: "memory")
#define CP_WAIT1()  asm volatile("cp.async.wait_group 1;"  ::: "memory")

__device__ __forceinline__ void ldsm_x4(uint32_t* r, uint32_t addr) {
    asm volatile("ldmatrix.sync.aligned.m8n8.x4.shared.b16 {%0,%1,%2,%3}, [%4];"
        : "=r"(r[0]), "=r"(r[1]), "=r"(r[2]), "=r"(r[3]) : "r"(addr));
}
__device__ __forceinline__ void mma16816(float* c, const uint32_t* a,
                                         uint32_t b0, uint32_t b1) {
    asm volatile(
        "mma.sync.aligned.m16n8k16.row.col.f32.bf16.bf16.f32 "
        "{%0,%1,%2,%3}, {%4,%5,%6,%7}, {%8,%9}, {%0,%1,%2,%3};"
        : "+f"(c[0]), "+f"(c[1]), "+f"(c[2]), "+f"(c[3])
        : "r"(a[0]), "r"(a[1]), "r"(a[2]), "r"(a[3]), "r"(b0), "r"(b1));
}
__device__ __forceinline__ void mma_f8h(uint32_t* c, const uint32_t* a,
                                        uint32_t b0, uint32_t b1) {
    asm volatile(
        "mma.sync.aligned.m16n8k32.row.col.f16.e4m3.e4m3.f16 "
        "{%0,%1}, {%2,%3,%4,%5}, {%6,%7}, {%0,%1};"
        : "+r"(c[0]), "+r"(c[1])
        : "r"(a[0]), "r"(a[1]), "r"(a[2]), "r"(a[3]), "r"(b0), "r"(b1));
}
__device__ __forceinline__ uint16_t f2_to_e4m3x2(float x0, float x1) {
    return (uint16_t)__nv_cvt_float2_to_fp8x2(make_float2(x0, x1),
                                              __NV_SATFINITE, __NV_E4M3);
}

// ---------------------------------------------------------------------------
// GroupNorm -> bf16 [c, hw]
// ---------------------------------------------------------------------------
__global__ __launch_bounds__(256) void groupnorm_kernel(
    const float* __restrict__ x, const float* __restrict__ scale,
    const float* __restrict__ bias, __nv_bfloat16* __restrict__ xn)
{
    const int b = blockIdx.x / NGRP, g = blockIdx.x % NGRP;
    const size_t base = ((size_t)b * CH + (size_t)g * CPG) * HW;
    const int n4 = CPG * HW / 4;

    const float4* xin = reinterpret_cast<const float4*>(x + base);
    float s = 0.f, ss = 0.f;
    for (int i = threadIdx.x; i < n4; i += 256) {
        float4 t = xin[i];
        s  += t.x + t.y + t.z + t.w;
        ss += t.x * t.x + t.y * t.y + t.z * t.z + t.w * t.w;
    }
    __shared__ float r1[256], r2[256];
    r1[threadIdx.x] = s; r2[threadIdx.x] = ss;
    __syncthreads();
    for (int off = 128; off > 0; off >>= 1) {
        if (threadIdx.x < off) {
            r1[threadIdx.x] += r1[threadIdx.x + off];
            r2[threadIdx.x] += r2[threadIdx.x + off];
        }
        __syncthreads();
    }
    const float inv_n = 1.f / (float)(CPG * HW);
    const float mean = r1[0] * inv_n;
    const float var  = fmaxf(r2[0] * inv_n - mean * mean, 0.f);
    const float rstd = rsqrtf(var + 1e-6f);

    uint2* xo = reinterpret_cast<uint2*>(xn + base);
    for (int i = threadIdx.x; i < n4; i += 256) {
        const int c = g * CPG + (i >> 10);
        const float a = scale[c] * rstd;
        const float d = bias[c] - mean * a;
        float4 t = xin[i];
        __nv_bfloat162 h0 = __floats2bfloat162_rn(t.x * a + d, t.y * a + d);
        __nv_bfloat162 h1 = __floats2bfloat162_rn(t.z * a + d, t.w * a + d);
        uint2 o;
        o.x = *reinterpret_cast<uint32_t*>(&h0);
        o.y = *reinterpret_cast<uint32_t*>(&h1);
        xo[i] = o;
    }
}

// ---------------------------------------------------------------------------
// 16-bit transpose [R, C] -> [C, R]
// ---------------------------------------------------------------------------
__global__ __launch_bounds__(256) void transpose_h16(
    const uint16_t* __restrict__ in, uint16_t* __restrict__ out, int R, int C)
{
    __shared__ uint16_t tile[64][72];
    const size_t zoff = (size_t)blockIdx.z * (size_t)R * C;
    const int r0 = blockIdx.y * 64, c0 = blockIdx.x * 64;

    #pragma unroll
    for (int it = 0; it < 2; it++) {
        int idx = threadIdx.x + it * 256;
        int r = idx >> 3, c8 = idx & 7;
        uint4 v = *reinterpret_cast<const uint4*>(in + zoff + (size_t)(r0 + r) * C + c0 + c8 * 8);
        *reinterpret_cast<uint4*>(&tile[r][c8 * 8]) = v;
    }
    __syncthreads();
    #pragma unroll
    for (int it = 0; it < 2; it++) {
        int idx = threadIdx.x + it * 256;
        int c = idx >> 3, r8 = idx & 7;
        uint16_t tmp[8];
        #pragma unroll
        for (int i = 0; i < 8; i++) tmp[i] = tile[r8 * 8 + i][c];
        *reinterpret_cast<uint4*>(out + zoff + (size_t)(c0 + c) * R + r0 + r8 * 8) =
            *reinterpret_cast<uint4*>(tmp);
    }
}

// ---------------------------------------------------------------------------
// weights fp32 -> bf16
// ---------------------------------------------------------------------------
__global__ __launch_bounds__(256) void cvt_w_kernel(
    const float* __restrict__ a, const float* __restrict__ b,
    const float* __restrict__ c, const float* __restrict__ d,
    __nv_bfloat16* __restrict__ w)
{
    const int i = blockIdx.x * 256 + threadIdx.x;
    const float* s = (blockIdx.y == 0) ? a : (blockIdx.y == 1) ? b : (blockIdx.y == 2) ? c : d;
    w[(size_t)blockIdx.y * CC + i] = __float2bfloat16(s[i]);
}

// ---------------------------------------------------------------------------
// bf16 GEMM (QKV + proj): D[M,N] = alpha*A@B^T + bias_m + bias_n + addc
// OT: 0 = fp32 out, 2 = fp8 out. 128x128 tile, 8 warps 4Mx2N, 3 stages.
// ---------------------------------------------------------------------------
#define PITCH  144
#define OPSZ   18432
#define STG_SZ 36864
#define SMEM_TC 110592

template<int OT>
__global__ void __launch_bounds__(256, 2) gemm_tc(
    const void* __restrict__ Ag, const void* __restrict__ Bg,
    void* __restrict__ Cout,
    const float* __restrict__ bias_m, const float* __restrict__ bias_n,
    int M, int N, int K, float alpha, float addc,
    size_t sA, size_t sB, size_t sC)
{
    extern __shared__ __align__(16) char smem[];
    const uint32_t sb = smem_u32(smem);

    const int tid  = threadIdx.x;
    const int lane = tid & 31;
    const int wid  = tid >> 5;
    const int wm   = wid >> 1;
    const int wn   = wid & 1;
    const int bm = blockIdx.y * 128;
    const int bn = blockIdx.x * 128;

    const uint8_t* Ab = (const uint8_t*)Ag + ((size_t)blockIdx.z * sA + (size_t)bm * K) * 2;
    const uint8_t* Bb = (const uint8_t*)Bg + ((size_t)blockIdx.z * sB + (size_t)bn * K) * 2;

    int rr[4];
    uint32_t so[4], go[4];
    #pragma unroll
    for (int j = 0; j < 4; j++) {
        const int idx = tid + j * 256;
        rr[j] = idx >> 3;
        const int cc = idx & 7;
        so[j] = (uint32_t)rr[j] * PITCH + cc * 16;
        go[j] = cc * 16;
    }

    const int nk = K >> 6;

    #pragma unroll
    for (int s = 0; s < 2; s++) {
        const uint32_t kb = (uint32_t)s * 128;
        const uint32_t st = sb + s * STG_SZ;
        #pragma unroll
        for (int j = 0; j < 4; j++) {
            cp16(st + so[j],        Ab + (size_t)rr[j] * K * 2 + kb + go[j]);
            cp16(st + OPSZ + so[j], Bb + (size_t)rr[j] * K * 2 + kb + go[j]);
        }
        CP_COMMIT();
    }

    float acc[2][8][4];
    #pragma unroll
    for (int i = 0; i < 2; i++)
        #pragma unroll
        for (int j = 0; j < 8; j++)
            #pragma unroll
            for (int t = 0; t < 4; t++) acc[i][j][t] = 0.f;

    const uint32_t lrow = lane & 15;
    const uint32_t lsel = (lane >> 4) * 16;

    int buf = 0;
    for (int ck = 0; ck < nk; ck++) {
        CP_WAIT1();
        __syncthreads();

        if (ck + 2 < nk) {
            const uint32_t kb = (uint32_t)(ck + 2) * 128;
            const uint32_t st = sb + ((buf + 2) % 3) * STG_SZ;
            #pragma unroll
            for (int j = 0; j < 4; j++) {
                cp16(st + so[j],        Ab + (size_t)rr[j] * K * 2 + kb + go[j]);
                cp16(st + OPSZ + so[j], Bb + (size_t)rr[j] * K * 2 + kb + go[j]);
            }
        }
        CP_COMMIT();

        const uint32_t sa  = sb + buf * STG_SZ;
        const uint32_t sbm = sa + OPSZ;
        #pragma unroll
        for (int kf = 0; kf < 4; kf++) {
            const uint32_t kofs = kf * 32 + lsel;
            uint32_t ar[2][4];
            #pragma unroll
            for (int mi = 0; mi < 2; mi++)
                ldsm_x4(ar[mi], sa + (wm * 32 + mi * 16 + lrow) * PITCH + kofs);
            uint32_t br[4][4];
            #pragma unroll
            for (int nb = 0; nb < 4; nb++)
                ldsm_x4(br[nb], sbm + (wn * 64 + nb * 16 + lrow) * PITCH + kofs);
            #pragma unroll
            for (int mi = 0; mi < 2; mi++)
                #pragma unroll
                for (int nj = 0; nj < 8; nj++) {
                    const int nb = nj >> 1, od = nj & 1;
                    mma16816(acc[mi][nj], ar[mi], br[nb][od], br[nb][od + 2]);
                }
        }
        buf = (buf + 1) % 3;
    }

    const int gid = lane >> 2, tig = lane & 3;
    #pragma unroll
    for (int mi = 0; mi < 2; mi++) {
        #pragma unroll
        for (int r2 = 0; r2 < 2; r2++) {
            const int m = bm + wm * 32 + mi * 16 + gid + r2 * 8;
            const float bmv = (bias_m ? bias_m[m] : 0.f) + addc;
            #pragma unroll
            for (int nj = 0; nj < 8; nj++) {
                const int n = bn + wn * 64 + nj * 8 + tig * 2;
                float x0 = acc[mi][nj][r2 * 2]     * alpha + bmv;
                float x1 = acc[mi][nj][r2 * 2 + 1] * alpha + bmv;
                if (bias_n) { x0 += bias_n[n]; x1 += bias_n[n + 1]; }
                const size_t off = (size_t)blockIdx.z * sC + (size_t)m * N + n;
                if (OT == 0) {
                    *reinterpret_cast<float2*>((float*)Cout + off) = make_float2(x0, x1);
                } else {
                    *reinterpret_cast<uint16_t*>((uint8_t*)Cout + off)
                        = f2_to_e4m3x2(x0, x1);
                }
            }
        }
    }
}

// ---------------------------------------------------------------------------
// fp8 attention GEMM, f16 acc: 128x128 tile, 4 warps (2x2 of 64x64),
// 128 threads, 128-fp8 K-chunks, 3-stage cp.async.
// MODE 0 (scores): p = exp2(s*sc) -> fp8 out, + deterministic partial
//                  row sums to ps[b][jt][m].
// MODE 1 (attnV):  bf16 out scaled by 1/rsum[b][m].
// ---------------------------------------------------------------------------
template<int MODE>
__global__ void __launch_bounds__(128, 2) gemm_f8h(
    const uint8_t* __restrict__ A, const uint8_t* __restrict__ B,
    void* __restrict__ C,
    float* __restrict__ ps, const float* __restrict__ rsum,
    int M, int N, int K, float sc,
    size_t sA, size_t sB, size_t sC)
{
    extern __shared__ __align__(16) char smem[];
    const uint32_t sb = smem_u32(smem);

    const int tid  = threadIdx.x;
    const int lane = tid & 31;
    const int wid  = tid >> 5;
    const int wm   = wid >> 1;
    const int wn   = wid & 1;
    const int bm = blockIdx.y * 128;
    const int bn = blockIdx.x * 128;

    const uint8_t* Ab = A + (size_t)blockIdx.z * sA + (size_t)bm * K;
    const uint8_t* Bb = B + (size_t)blockIdx.z * sB + (size_t)bn * K;

    uint32_t so[8], gAo[8];
    #pragma unroll
    for (int j = 0; j < 8; j++) {
        const int idx = tid + j * 128;
        const int row = idx >> 3, cc = idx & 7;
        so[j]  = (uint32_t)row * PITCH + cc * 16;
        gAo[j] = (uint32_t)row * K + cc * 16;
    }

    const int nk = K >> 7;

    #pragma unroll
    for (int s = 0; s < 2; s++) {
        const uint32_t kb = (uint32_t)s * 128;
        const uint32_t st = sb + s * STG_SZ;
        #pragma unroll
        for (int j = 0; j < 8; j++) {
            cp16(st + so[j],        Ab + gAo[j] + kb);
            cp16(st + OPSZ + so[j], Bb + gAo[j] + kb);
        }
        CP_COMMIT();
    }

    uint32_t acc[4][8][2];
    #pragma unroll
    for (int i = 0; i < 4; i++)
        #pragma unroll
        for (int j = 0; j < 8; j++) { acc[i][j][0] = 0u; acc[i][j][1] = 0u; }

    const uint32_t lrow = lane & 15;
    const uint32_t lsel = (lane >> 4) * 16;

    int buf = 0;
    for (int ck = 0; ck < nk; ck++) {
        CP_WAIT1();
        __syncthreads();

        if (ck + 2 < nk) {
            const uint32_t kb = (uint32_t)(ck + 2) * 128;
            const uint32_t st = sb + ((buf + 2) % 3) * STG_SZ;
            #pragma unroll
            for (int j = 0; j < 8; j++) {
                cp16(st + so[j],        Ab + gAo[j] + kb);
                cp16(st + OPSZ + so[j], Bb + gAo[j] + kb);
            }
        }
        CP_COMMIT();

        const uint32_t sa  = sb + buf * STG_SZ;
        const uint32_t sbm = sa + OPSZ;
        #pragma unroll
        for (int kf = 0; kf < 4; kf++) {
            const uint32_t kofs = kf * 32 + lsel;
            uint32_t ar[4][4];
            #pragma unroll
            for (int mi = 0; mi < 4; mi++)
                ldsm_x4(ar[mi], sa + (wm * 64 + mi * 16 + lrow) * PITCH + kofs);
            uint32_t br[4][4];
            #pragma unroll
            for (int nb = 0; nb < 4; nb++)
                ldsm_x4(br[nb], sbm + (wn * 64 + nb * 16 + lrow) * PITCH + kofs);
            #pragma unroll
            for (int mi = 0; mi < 4; mi++)
                #pragma unroll
                for (int nj = 0; nj < 8; nj++) {
                    const int nb = nj >> 1, od = nj & 1;
                    mma_f8h(acc[mi][nj], ar[mi], br[nb][od], br[nb][od + 2]);
                }
        }
        buf = (buf + 1) % 3;
    }

    const int gid = lane >> 2, tig = lane & 3;

    if (MODE == 0) {
        // scores: exp epilogue + fp8 store + partial row sums
        float lsum[4][2];
        #pragma unroll
        for (int mi = 0; mi < 4; mi++) { lsum[mi][0] = 0.f; lsum[mi][1] = 0.f; }

        #pragma unroll
        for (int mi = 0; mi < 4; mi++) {
            #pragma unroll
            for (int r2 = 0; r2 < 2; r2++) {
                const int m = bm + wm * 64 + mi * 16 + gid + r2 * 8;
                #pragma unroll
                for (int nj = 0; nj < 8; nj++) {
                    const int n = bn + wn * 64 + nj * 8 + tig * 2;
                    const __half2 h = *reinterpret_cast<const __half2*>(&acc[mi][nj][r2]);
                    const float2 f = __half22float2(h);
                    const float p0 = exp2f(f.x * sc);
                    const float p1 = exp2f(f.y * sc);
                    lsum[mi][r2] += p0 + p1;
                    *reinterpret_cast<uint16_t*>(
                        (uint8_t*)C + (size_t)blockIdx.z * sC + (size_t)m * N + n)
                        = f2_to_e4m3x2(p0, p1);
                }
            }
        }
        // deterministic partial-sum combine (reuse smem after all warps exit loop)
        float* pss = reinterpret_cast<float*>(smem);
        __syncthreads();
        #pragma unroll
        for (int mi = 0; mi < 4; mi++) {
            #pragma unroll
            for (int r2 = 0; r2 < 2; r2++) {
                float v = lsum[mi][r2];
                v += __shfl_xor_sync(0xffffffffu, v, 1);
                v += __shfl_xor_sync(0xffffffffu, v, 2);
                if (tig == 0)
                    pss[wn * 128 + wm * 64 + mi * 16 + gid + r2 * 8] = v;
            }
        }
        __syncthreads();
        // 128 threads, one row each: combine the two n-half warps, write global
        ps[((size_t)blockIdx.z * gridDim.x + blockIdx.x) * (size_t)M + bm + tid]
            = pss[tid] + pss[128 + tid];
    } else {
        // attnV: scale by 1/rsum[b][m], bf16 store
        #pragma unroll
        for (int mi = 0; mi < 4; mi++) {
            #pragma unroll
            for (int r2 = 0; r2 < 2; r2++) {
                const int m = bm + wm * 64 + mi * 16 + gid + r2 * 8;
                const float scale = __fdividef(1.f, rsum[(size_t)blockIdx.z * M + m]);
                #pragma unroll
                for (int nj = 0; nj < 8; nj++) {
                    const int n = bn + wn * 64 + nj * 8 + tig * 2;
                    const __half2 h = *reinterpret_cast<const __half2*>(&acc[mi][nj][r2]);
                    const float2 f = __half22float2(h);
                    __nv_bfloat162 ob = __floats2bfloat162_rn(f.x * scale, f.y * scale);
                    *reinterpret_cast<uint32_t*>(
                        (__nv_bfloat16*)C + (size_t)blockIdx.z * sC + (size_t)m * N + n)
                        = *reinterpret_cast<uint32_t*>(&ob);
                }
            }
        }
    }
}

// ---------------------------------------------------------------------------
// rsum[b][i] = sum over 32 j-tiles of partial sums
// ---------------------------------------------------------------------------
__global__ __launch_bounds__(256) void rsum_kernel(
    const float* __restrict__ ps, float* __restrict__ rsum)
{
    const int i = blockIdx.x * 256 + threadIdx.x;   // 0 .. BATCH*HW-1
    const int b = i >> 12, r = i & (HW - 1);
    float s = 0.f;
    #pragma unroll
    for (int jt = 0; jt < NJT; jt++)
        s += ps[((size_t)b * NJT + jt) * HW + r];
    rsum[i] = s;
}

// ---------------------------------------------------------------------------
// Launch
// ---------------------------------------------------------------------------
extern "C" void kernel_launch(void* const* d_in, const int* in_sizes, int n_in,
                              void* d_out, int out_size)
{
    const float* x  = (const float*)d_in[0];
    const float* gs = (const float*)d_in[1];
    const float* gb = (const float*)d_in[2];
    const float* wq = (const float*)d_in[3];
    const float* bq = (const float*)d_in[4];
    const float* wk = (const float*)d_in[5];
    const float* bk = (const float*)d_in[6];
    const float* wv = (const float*)d_in[7];
    const float* bv = (const float*)d_in[8];
    const float* wp = (const float*)d_in[9];
    const float* bp = (const float*)d_in[10];
    float* out = (float*)d_out;

    __nv_bfloat16 *xn, *xnT, *o2, *w;
    uint8_t *q, *k, *v, *at;
    float *ps, *rsum;
    cudaGetSymbolAddress((void**)&xn,   g_xn);
    cudaGetSymbolAddress((void**)&xnT,  g_xnT);
    cudaGetSymbolAddress((void**)&q,    g_q);
    cudaGetSymbolAddress((void**)&k,    g_k);
    cudaGetSymbolAddress((void**)&v,    g_v);
    cudaGetSymbolAddress((void**)&at,   g_at);
    cudaGetSymbolAddress((void**)&o2,   g_o2);
    cudaGetSymbolAddress((void**)&w,    g_w);
    cudaGetSymbolAddress((void**)&ps,   g_ps);
    cudaGetSymbolAddress((void**)&rsum, g_rsum);

    cudaFuncSetAttribute(gemm_tc<2>,  cudaFuncAttributeMaxDynamicSharedMemorySize, SMEM_TC);
    cudaFuncSetAttribute(gemm_tc<0>,  cudaFuncAttributeMaxDynamicSharedMemorySize, SMEM_TC);
    cudaFuncSetAttribute(gemm_f8h<0>, cudaFuncAttributeMaxDynamicSharedMemorySize, SMEM_TC);
    cudaFuncSetAttribute(gemm_f8h<1>, cudaFuncAttributeMaxDynamicSharedMemorySize, SMEM_TC);

    // 0) weights -> bf16
    cvt_w_kernel<<<dim3(CC / 256, 4), 256>>>(wq, wk, wv, wp, w);

    // 1) GroupNorm -> bf16 [c, hw]
    groupnorm_kernel<<<BATCH * NGRP, 256>>>(x, gs, gb, xn);

    // 2) transpose xn -> xnT [hw, c]
    transpose_h16<<<dim3(HW / 64, CH / 64, BATCH), 256>>>(
        (const uint16_t*)xn, (uint16_t*)xnT, CH, HW);

    // 3) Q, K -> fp8 [hw, c]  (bias over N)
    dim3 gQK(CH / 128, HW / 128, BATCH);
    gemm_tc<2><<<gQK, 256, SMEM_TC>>>(xnT, w,      q, nullptr, bq, HW, CH, CH, 1.f, 0.f, CHW, 0, CHW);
    gemm_tc<2><<<gQK, 256, SMEM_TC>>>(xnT, w + CC, k, nullptr, bk, HW, CH, CH, 1.f, 0.f, CHW, 0, CHW);

    // 4) V -> fp8 [c, hw]  (bias over M)
    dim3 gV(HW / 128, CH / 128, BATCH);
    gemm_tc<2><<<gV, 256, SMEM_TC>>>(w + 2 * CC, xnT, v, bv, nullptr, CH, HW, CH, 1.f, 0.f, 0, CHW, CHW);

    // 5) scores + exp fused -> fp8 p, partial row sums
    const float sc = 1.4426950408f / sqrtf((float)CH);   // alpha * log2(e)
    dim3 gS(HW / 128, HW / 128, BATCH);
    gemm_f8h<0><<<gS, 128, SMEM_TC>>>(q, k, at, ps, nullptr,
                                      HW, HW, CH, sc, CHW, CHW, SHW);

    // 6) reduce partials -> rsum
    rsum_kernel<<<BATCH * HW / 256, 256>>>(ps, rsum);

    // 7) o2[hw, c] = (p @ v^T) / rsum  (normalization fused into epilogue)
    dim3 gO(CH / 128, HW / 128, BATCH);
    gemm_f8h<1><<<gO, 128, SMEM_TC>>>(at, v, o2, nullptr, rsum,
                                      HW, CH, HW, 0.f, SHW, CHW, CHW);

    // 8) proj fp32 + bias + 64
    gemm_tc<0><<<gV, 256, SMEM_TC>>>(w + 3 * CC, o2, out, bp, nullptr,
                                     CH, HW, CH, 1.f, 64.0f, 0, CHW, CHW);
}

// round 11
// speedup vs baseline: 1.0887x; 1.0294x over previous
#include <cuda_runtime.h>
#include <cuda_bf16.h>
#include <cuda_fp16.h>
#include <cuda_fp8.h>
#include <cstdint>
#include <math.h>

#define BATCH 4
#define CH    512
#define HW    4096
#define NGRP  32
#define CPG   16
#define NJT   (HW / 128)

static const size_t CHW = (size_t)CH * HW;
static const size_t SHW = (size_t)HW * HW;
#define CC (CH * CH)

// ---------------- scratch ----------------
__device__ __nv_bfloat16 g_xn  [BATCH * CH * HW];   // [c, hw] bf16
__device__ __nv_bfloat16 g_xnT [BATCH * CH * HW];   // [hw, c] bf16
__device__ uint8_t       g_q   [BATCH * CH * HW];   // [hw, c] fp8
__device__ uint8_t       g_k   [BATCH * CH * HW];   // [hw, c] fp8
__device__ uint8_t       g_v   [BATCH * CH * HW];   // [c, hw] fp8
__device__ uint8_t       g_at  [BATCH * HW * HW];   // fp8 p = exp(alpha*s)
__device__ uint8_t       g_o28 [BATCH * CH * HW];   // [hw, c] fp8, x256
__device__ __nv_bfloat16 g_w   [4 * CH * CH];       // wq, wk, wv, wp bf16
__device__ uint8_t       g_w8  [CH * CH];           // wp fp8, x64
__device__ float         g_bqk [1024];              // concat(bq, bk)
__device__ float         g_ps  [BATCH * NJT * HW];  // partial row sums
__device__ float         g_rsum[BATCH * HW];        // softmax denominators

// ---------------- PTX helpers (family-portable) ----------------
__device__ __forceinline__ uint32_t smem_u32(const void* p) {
    uint32_t a;
    asm("{ .reg .u64 t; cvta.to.shared.u64 t, %1; cvt.u32.u64 %0, t; }"
        : "=r"(a) : "l"(p));
    return a;
}
__device__ __forceinline__ void cp16(uint32_t s, const void* g) {
    asm volatile("cp.async.cg.shared.global [%0], [%1], 16;"
                 :: "r"(s), "l"(__cvta_generic_to_global(g)) : "memory");
}
#define CP_COMMIT() asm volatile("cp.async.commit_group;" ::: "memory")
#define CP_WAIT1()  asm volatile("cp.async.wait_group 1;"  ::: "memory")

__device__ __forceinline__ void ldsm_x4(uint32_t* r, uint32_t addr) {
    asm volatile("ldmatrix.sync.aligned.m8n8.x4.shared.b16 {%0,%1,%2,%3}, [%4];"
        : "=r"(r[0]), "=r"(r[1]), "=r"(r[2]), "=r"(r[3]) : "r"(addr));
}
__device__ __forceinline__ void mma16816(float* c, const uint32_t* a,
                                         uint32_t b0, uint32_t b1) {
    asm volatile(
        "mma.sync.aligned.m16n8k16.row.col.f32.bf16.bf16.f32 "
        "{%0,%1,%2,%3}, {%4,%5,%6,%7}, {%8,%9}, {%0,%1,%2,%3};"
        : "+f"(c[0]), "+f"(c[1]), "+f"(c[2]), "+f"(c[3])
        : "r"(a[0]), "r"(a[1]), "r"(a[2]), "r"(a[3]), "r"(b0), "r"(b1));
}
__device__ __forceinline__ void mma_f8h(uint32_t* c, const uint32_t* a,
                                        uint32_t b0, uint32_t b1) {
    asm volatile(
        "mma.sync.aligned.m16n8k32.row.col.f16.e4m3.e4m3.f16 "
        "{%0,%1}, {%2,%3,%4,%5}, {%6,%7}, {%0,%1};"
        : "+r"(c[0]), "+r"(c[1])
        : "r"(a[0]), "r"(a[1]), "r"(a[2]), "r"(a[3]), "r"(b0), "r"(b1));
}
__device__ __forceinline__ uint16_t f2_to_e4m3x2(float x0, float x1) {
    return (uint16_t)__nv_cvt_float2_to_fp8x2(make_float2(x0, x1),
                                              __NV_SATFINITE, __NV_E4M3);
}

// ---------------------------------------------------------------------------
// GroupNorm -> bf16 [c, hw]
// ---------------------------------------------------------------------------
__global__ __launch_bounds__(256) void groupnorm_kernel(
    const float* __restrict__ x, const float* __restrict__ scale,
    const float* __restrict__ bias, __nv_bfloat16* __restrict__ xn)
{
    const int b = blockIdx.x / NGRP, g = blockIdx.x % NGRP;
    const size_t base = ((size_t)b * CH + (size_t)g * CPG) * HW;
    const int n4 = CPG * HW / 4;

    const float4* xin = reinterpret_cast<const float4*>(x + base);
    float s = 0.f, ss = 0.f;
    for (int i = threadIdx.x; i < n4; i += 256) {
        float4 t = xin[i];
        s  += t.x + t.y + t.z + t.w;
        ss += t.x * t.x + t.y * t.y + t.z * t.z + t.w * t.w;
    }
    __shared__ float r1[256], r2[256];
    r1[threadIdx.x] = s; r2[threadIdx.x] = ss;
    __syncthreads();
    for (int off = 128; off > 0; off >>= 1) {
        if (threadIdx.x < off) {
            r1[threadIdx.x] += r1[threadIdx.x + off];
            r2[threadIdx.x] += r2[threadIdx.x + off];
        }
        __syncthreads();
    }
    const float inv_n = 1.f / (float)(CPG * HW);
    const float mean = r1[0] * inv_n;
    const float var  = fmaxf(r2[0] * inv_n - mean * mean, 0.f);
    const float rstd = rsqrtf(var + 1e-6f);

    uint2* xo = reinterpret_cast<uint2*>(xn + base);
    for (int i = threadIdx.x; i < n4; i += 256) {
        const int c = g * CPG + (i >> 10);
        const float a = scale[c] * rstd;
        const float d = bias[c] - mean * a;
        float4 t = xin[i];
        __nv_bfloat162 h0 = __floats2bfloat162_rn(t.x * a + d, t.y * a + d);
        __nv_bfloat162 h1 = __floats2bfloat162_rn(t.z * a + d, t.w * a + d);
        uint2 o;
        o.x = *reinterpret_cast<uint32_t*>(&h0);
        o.y = *reinterpret_cast<uint32_t*>(&h1);
        xo[i] = o;
    }
}

// ---------------------------------------------------------------------------
// 16-bit transpose [R, C] -> [C, R]
// ---------------------------------------------------------------------------
__global__ __launch_bounds__(256) void transpose_h16(
    const uint16_t* __restrict__ in, uint16_t* __restrict__ out, int R, int C)
{
    __shared__ uint16_t tile[64][72];
    const size_t zoff = (size_t)blockIdx.z * (size_t)R * C;
    const int r0 = blockIdx.y * 64, c0 = blockIdx.x * 64;

    #pragma unroll
    for (int it = 0; it < 2; it++) {
        int idx = threadIdx.x + it * 256;
        int r = idx >> 3, c8 = idx & 7;
        uint4 v = *reinterpret_cast<const uint4*>(in + zoff + (size_t)(r0 + r) * C + c0 + c8 * 8);
        *reinterpret_cast<uint4*>(&tile[r][c8 * 8]) = v;
    }
    __syncthreads();
    #pragma unroll
    for (int it = 0; it < 2; it++) {
        int idx = threadIdx.x + it * 256;
        int c = idx >> 3, r8 = idx & 7;
        uint16_t tmp[8];
        #pragma unroll
        for (int i = 0; i < 8; i++) tmp[i] = tile[r8 * 8 + i][c];
        *reinterpret_cast<uint4*>(out + zoff + (size_t)(c0 + c) * R + r0 + r8 * 8) =
            *reinterpret_cast<uint4*>(tmp);
    }
}

// ---------------------------------------------------------------------------
// weights: fp32 -> bf16; wp also -> fp8 x64; concat(bq,bk)
// ---------------------------------------------------------------------------
__global__ __launch_bounds__(256) void cvt_w_kernel(
    const float* __restrict__ a, const float* __restrict__ b,
    const float* __restrict__ c, const float* __restrict__ d,
    const float* __restrict__ bq, const float* __restrict__ bk,
    __nv_bfloat16* __restrict__ w, uint8_t* __restrict__ w8,
    float* __restrict__ bqk)
{
    const int i = blockIdx.x * 256 + threadIdx.x;
    const float* s = (blockIdx.y == 0) ? a : (blockIdx.y == 1) ? b : (blockIdx.y == 2) ? c : d;
    const float val = s[i];
    w[(size_t)blockIdx.y * CC + i] = __float2bfloat16(val);
    if (blockIdx.y == 3)
        w8[i] = (uint8_t)__nv_cvt_float_to_fp8(val * 64.f, __NV_SATFINITE, __NV_E4M3);
    if (blockIdx.y == 0 && i < 1024)
        bqk[i] = (i < 512) ? bq[i] : bk[i - 512];
}

// ---------------------------------------------------------------------------
// bf16 GEMM: D = A@B^T + bias_n. OT 2 = fp8 out; OT 3 = dual fp8 out
// (n<512 -> Cout, else Cout2; each 512 wide). 128x128 tile, 8 warps, 3 stages.
// ---------------------------------------------------------------------------
#define PITCH  144
#define OPSZ   18432
#define STG_SZ 36864
#define SMEM_TC 110592

template<int OT>
__global__ void __launch_bounds__(256, 2) gemm_tc(
    const void* __restrict__ Ag, const void* __restrict__ Bg,
    void* __restrict__ Cout, void* __restrict__ Cout2,
    const float* __restrict__ bias_m, const float* __restrict__ bias_n,
    int M, int N, int K, float alpha,
    size_t sA, size_t sB, size_t sC)
{
    extern __shared__ __align__(16) char smem[];
    const uint32_t sb = smem_u32(smem);

    const int tid  = threadIdx.x;
    const int lane = tid & 31;
    const int wid  = tid >> 5;
    const int wm   = wid >> 1;
    const int wn   = wid & 1;
    const int bm = blockIdx.y * 128;
    const int bn = blockIdx.x * 128;

    const uint8_t* Ab = (const uint8_t*)Ag + ((size_t)blockIdx.z * sA + (size_t)bm * K) * 2;
    const uint8_t* Bb = (const uint8_t*)Bg + ((size_t)blockIdx.z * sB + (size_t)bn * K) * 2;

    int rr[4];
    uint32_t so[4], go[4];
    #pragma unroll
    for (int j = 0; j < 4; j++) {
        const int idx = tid + j * 256;
        rr[j] = idx >> 3;
        const int cc = idx & 7;
        so[j] = (uint32_t)rr[j] * PITCH + cc * 16;
        go[j] = cc * 16;
    }

    const int nk = K >> 6;

    #pragma unroll
    for (int s = 0; s < 2; s++) {
        const uint32_t kb = (uint32_t)s * 128;
        const uint32_t st = sb + s * STG_SZ;
        #pragma unroll
        for (int j = 0; j < 4; j++) {
            cp16(st + so[j],        Ab + (size_t)rr[j] * K * 2 + kb + go[j]);
            cp16(st + OPSZ + so[j], Bb + (size_t)rr[j] * K * 2 + kb + go[j]);
        }
        CP_COMMIT();
    }

    float acc[2][8][4];
    #pragma unroll
    for (int i = 0; i < 2; i++)
        #pragma unroll
        for (int j = 0; j < 8; j++)
            #pragma unroll
            for (int t = 0; t < 4; t++) acc[i][j][t] = 0.f;

    const uint32_t lrow = lane & 15;
    const uint32_t lsel = (lane >> 4) * 16;

    int buf = 0;
    for (int ck = 0; ck < nk; ck++) {
        CP_WAIT1();
        __syncthreads();

        if (ck + 2 < nk) {
            const uint32_t kb = (uint32_t)(ck + 2) * 128;
            const uint32_t st = sb + ((buf + 2) % 3) * STG_SZ;
            #pragma unroll
            for (int j = 0; j < 4; j++) {
                cp16(st + so[j],        Ab + (size_t)rr[j] * K * 2 + kb + go[j]);
                cp16(st + OPSZ + so[j], Bb + (size_t)rr[j] * K * 2 + kb + go[j]);
            }
        }
        CP_COMMIT();

        const uint32_t sa  = sb + buf * STG_SZ;
        const uint32_t sbm = sa + OPSZ;
        #pragma unroll
        for (int kf = 0; kf < 4; kf++) {
            const uint32_t kofs = kf * 32 + lsel;
            uint32_t ar[2][4];
            #pragma unroll
            for (int mi = 0; mi < 2; mi++)
                ldsm_x4(ar[mi], sa + (wm * 32 + mi * 16 + lrow) * PITCH + kofs);
            uint32_t br[4][4];
            #pragma unroll
            for (int nb = 0; nb < 4; nb++)
                ldsm_x4(br[nb], sbm + (wn * 64 + nb * 16 + lrow) * PITCH + kofs);
            #pragma unroll
            for (int mi = 0; mi < 2; mi++)
                #pragma unroll
                for (int nj = 0; nj < 8; nj++) {
                    const int nb = nj >> 1, od = nj & 1;
                    mma16816(acc[mi][nj], ar[mi], br[nb][od], br[nb][od + 2]);
                }
        }
        buf = (buf + 1) % 3;
    }

    const int gid = lane >> 2, tig = lane & 3;
    #pragma unroll
    for (int mi = 0; mi < 2; mi++) {
        #pragma unroll
        for (int r2 = 0; r2 < 2; r2++) {
            const int m = bm + wm * 32 + mi * 16 + gid + r2 * 8;
            const float bmv = bias_m ? bias_m[m] : 0.f;
            #pragma unroll
            for (int nj = 0; nj < 8; nj++) {
                const int n = bn + wn * 64 + nj * 8 + tig * 2;
                float x0 = acc[mi][nj][r2 * 2]     * alpha + bmv;
                float x1 = acc[mi][nj][r2 * 2 + 1] * alpha + bmv;
                if (bias_n) { x0 += bias_n[n]; x1 += bias_n[n + 1]; }
                if (OT == 2) {
                    *reinterpret_cast<uint16_t*>(
                        (uint8_t*)Cout + (size_t)blockIdx.z * sC + (size_t)m * N + n)
                        = f2_to_e4m3x2(x0, x1);
                } else {  // OT == 3: split halves, each 512 wide
                    uint8_t* dst = (n < 512) ? (uint8_t*)Cout : (uint8_t*)Cout2;
                    *reinterpret_cast<uint16_t*>(
                        dst + (size_t)blockIdx.z * sC + (size_t)m * 512 + (n & 511))
                        = f2_to_e4m3x2(x0, x1);
                }
            }
        }
    }
}

// ---------------------------------------------------------------------------
// fp8 GEMM, f16 acc: 128x128 tile, 4 warps (2x2 of 64x64), 128 threads.
// MODE 0 (scores): p = exp2(s*sc) -> fp8, + partial row sums ps.
// MODE 1 (attnV):  fp8 out = acc * 256/rsum[m]   (o2 scaled x256)
// MODE 2 (proj):   fp32 out = acc * sc + bias_m[m] + addc
// ---------------------------------------------------------------------------
template<int MODE>
__global__ void __launch_bounds__(128, 2) gemm_f8h(
    const uint8_t* __restrict__ A, const uint8_t* __restrict__ B,
    void* __restrict__ C,
    float* __restrict__ ps, const float* __restrict__ rsum,
    const float* __restrict__ bias_m,
    int M, int N, int K, float sc, float addc,
    size_t sA, size_t sB, size_t sC)
{
    extern __shared__ __align__(16) char smem[];
    const uint32_t sb = smem_u32(smem);

    const int tid  = threadIdx.x;
    const int lane = tid & 31;
    const int wid  = tid >> 5;
    const int wm   = wid >> 1;
    const int wn   = wid & 1;
    const int bm = blockIdx.y * 128;
    const int bn = blockIdx.x * 128;

    const uint8_t* Ab = A + (size_t)blockIdx.z * sA + (size_t)bm * K;
    const uint8_t* Bb = B + (size_t)blockIdx.z * sB + (size_t)bn * K;

    uint32_t so[8], gAo[8];
    #pragma unroll
    for (int j = 0; j < 8; j++) {
        const int idx = tid + j * 128;
        const int row = idx >> 3, cc = idx & 7;
        so[j]  = (uint32_t)row * PITCH + cc * 16;
        gAo[j] = (uint32_t)row * K + cc * 16;
    }

    const int nk = K >> 7;

    #pragma unroll
    for (int s = 0; s < 2; s++) {
        const uint32_t kb = (uint32_t)s * 128;
        const uint32_t st = sb + s * STG_SZ;
        #pragma unroll
        for (int j = 0; j < 8; j++) {
            cp16(st + so[j],        Ab + gAo[j] + kb);
            cp16(st + OPSZ + so[j], Bb + gAo[j] + kb);
        }
        CP_COMMIT();
    }

    uint32_t acc[4][8][2];
    #pragma unroll
    for (int i = 0; i < 4; i++)
        #pragma unroll
        for (int j = 0; j < 8; j++) { acc[i][j][0] = 0u; acc[i][j][1] = 0u; }

    const uint32_t lrow = lane & 15;
    const uint32_t lsel = (lane >> 4) * 16;

    int buf = 0;
    for (int ck = 0; ck < nk; ck++) {
        CP_WAIT1();
        __syncthreads();

        if (ck + 2 < nk) {
            const uint32_t kb = (uint32_t)(ck + 2) * 128;
            const uint32_t st = sb + ((buf + 2) % 3) * STG_SZ;
            #pragma unroll
            for (int j = 0; j < 8; j++) {
                cp16(st + so[j],        Ab + gAo[j] + kb);
                cp16(st + OPSZ + so[j], Bb + gAo[j] + kb);
            }
        }
        CP_COMMIT();

        const uint32_t sa  = sb + buf * STG_SZ;
        const uint32_t sbm = sa + OPSZ;
        #pragma unroll
        for (int kf = 0; kf < 4; kf++) {
            const uint32_t kofs = kf * 32 + lsel;
            uint32_t ar[4][4];
            #pragma unroll
            for (int mi = 0; mi < 4; mi++)
                ldsm_x4(ar[mi], sa + (wm * 64 + mi * 16 + lrow) * PITCH + kofs);
            uint32_t br[4][4];
            #pragma unroll
            for (int nb = 0; nb < 4; nb++)
                ldsm_x4(br[nb], sbm + (wn * 64 + nb * 16 + lrow) * PITCH + kofs);
            #pragma unroll
            for (int mi = 0; mi < 4; mi++)
                #pragma unroll
                for (int nj = 0; nj < 8; nj++) {
                    const int nb = nj >> 1, od = nj & 1;
                    mma_f8h(acc[mi][nj], ar[mi], br[nb][od], br[nb][od + 2]);
                }
        }
        buf = (buf + 1) % 3;
    }

    const int gid = lane >> 2, tig = lane & 3;

    if (MODE == 0) {
        float lsum[4][2];
        #pragma unroll
        for (int mi = 0; mi < 4; mi++) { lsum[mi][0] = 0.f; lsum[mi][1] = 0.f; }

        #pragma unroll
        for (int mi = 0; mi < 4; mi++) {
            #pragma unroll
            for (int r2 = 0; r2 < 2; r2++) {
                const int m = bm + wm * 64 + mi * 16 + gid + r2 * 8;
                #pragma unroll
                for (int nj = 0; nj < 8; nj++) {
                    const int n = bn + wn * 64 + nj * 8 + tig * 2;
                    const __half2 h = *reinterpret_cast<const __half2*>(&acc[mi][nj][r2]);
                    const float2 f = __half22float2(h);
                    const float p0 = exp2f(f.x * sc);
                    const float p1 = exp2f(f.y * sc);
                    lsum[mi][r2] += p0 + p1;
                    *reinterpret_cast<uint16_t*>(
                        (uint8_t*)C + (size_t)blockIdx.z * sC + (size_t)m * N + n)
                        = f2_to_e4m3x2(p0, p1);
                }
            }
        }
        float* pss = reinterpret_cast<float*>(smem);
        __syncthreads();
        #pragma unroll
        for (int mi = 0; mi < 4; mi++) {
            #pragma unroll
            for (int r2 = 0; r2 < 2; r2++) {
                float v = lsum[mi][r2];
                v += __shfl_xor_sync(0xffffffffu, v, 1);
                v += __shfl_xor_sync(0xffffffffu, v, 2);
                if (tig == 0)
                    pss[wn * 128 + wm * 64 + mi * 16 + gid + r2 * 8] = v;
            }
        }
        __syncthreads();
        ps[((size_t)blockIdx.z * gridDim.x + blockIdx.x) * (size_t)M + bm + tid]
            = pss[tid] + pss[128 + tid];
    } else if (MODE == 1) {
        #pragma unroll
        for (int mi = 0; mi < 4; mi++) {
            #pragma unroll
            for (int r2 = 0; r2 < 2; r2++) {
                const int m = bm + wm * 64 + mi * 16 + gid + r2 * 8;
                const float scale = __fdividef(256.f, rsum[(size_t)blockIdx.z * M + m]);
                #pragma unroll
                for (int nj = 0; nj < 8; nj++) {
                    const int n = bn + wn * 64 + nj * 8 + tig * 2;
                    const __half2 h = *reinterpret_cast<const __half2*>(&acc[mi][nj][r2]);
                    const float2 f = __half22float2(h);
                    *reinterpret_cast<uint16_t*>(
                        (uint8_t*)C + (size_t)blockIdx.z * sC + (size_t)m * N + n)
                        = f2_to_e4m3x2(f.x * scale, f.y * scale);
                }
            }
        }
    } else {
        // proj: fp32 out + bias + addc
        #pragma unroll
        for (int mi = 0; mi < 4; mi++) {
            #pragma unroll
            for (int r2 = 0; r2 < 2; r2++) {
                const int m = bm + wm * 64 + mi * 16 + gid + r2 * 8;
                const float bmv = bias_m[m] + addc;
                #pragma unroll
                for (int nj = 0; nj < 8; nj++) {
                    const int n = bn + wn * 64 + nj * 8 + tig * 2;
                    const __half2 h = *reinterpret_cast<const __half2*>(&acc[mi][nj][r2]);
                    const float2 f = __half22float2(h);
                    *reinterpret_cast<float2*>(
                        (float*)C + (size_t)blockIdx.z * sC + (size_t)m * N + n)
                        = make_float2(f.x * sc + bmv, f.y * sc + bmv);
                }
            }
        }
    }
}

// ---------------------------------------------------------------------------
// rsum[b][i] = sum over 32 j-tiles of partial sums
// ---------------------------------------------------------------------------
__global__ __launch_bounds__(256) void rsum_kernel(
    const float* __restrict__ ps, float* __restrict__ rsum)
{
    const int i = blockIdx.x * 256 + threadIdx.x;
    const int b = i >> 12, r = i & (HW - 1);
    float s = 0.f;
    #pragma unroll
    for (int jt = 0; jt < NJT; jt++)
        s += ps[((size_t)b * NJT + jt) * HW + r];
    rsum[i] = s;
}

// ---------------------------------------------------------------------------
// Launch
// ---------------------------------------------------------------------------
extern "C" void kernel_launch(void* const* d_in, const int* in_sizes, int n_in,
                              void* d_out, int out_size)
{
    const float* x  = (const float*)d_in[0];
    const float* gs = (const float*)d_in[1];
    const float* gb = (const float*)d_in[2];
    const float* wq = (const float*)d_in[3];
    const float* bq = (const float*)d_in[4];
    const float* wk = (const float*)d_in[5];
    const float* bk = (const float*)d_in[6];
    const float* wv = (const float*)d_in[7];
    const float* bv = (const float*)d_in[8];
    const float* wp = (const float*)d_in[9];
    const float* bp = (const float*)d_in[10];
    float* out = (float*)d_out;

    __nv_bfloat16 *xn, *xnT, *w;
    uint8_t *q, *k, *v, *at, *o28, *w8;
    float *bqk, *ps, *rsum;
    cudaGetSymbolAddress((void**)&xn,   g_xn);
    cudaGetSymbolAddress((void**)&xnT,  g_xnT);
    cudaGetSymbolAddress((void**)&q,    g_q);
    cudaGetSymbolAddress((void**)&k,    g_k);
    cudaGetSymbolAddress((void**)&v,    g_v);
    cudaGetSymbolAddress((void**)&at,   g_at);
    cudaGetSymbolAddress((void**)&o28,  g_o28);
    cudaGetSymbolAddress((void**)&w,    g_w);
    cudaGetSymbolAddress((void**)&w8,   g_w8);
    cudaGetSymbolAddress((void**)&bqk,  g_bqk);
    cudaGetSymbolAddress((void**)&ps,   g_ps);
    cudaGetSymbolAddress((void**)&rsum, g_rsum);

    cudaFuncSetAttribute(gemm_tc<2>,  cudaFuncAttributeMaxDynamicSharedMemorySize, SMEM_TC);
    cudaFuncSetAttribute(gemm_tc<3>,  cudaFuncAttributeMaxDynamicSharedMemorySize, SMEM_TC);
    cudaFuncSetAttribute(gemm_f8h<0>, cudaFuncAttributeMaxDynamicSharedMemorySize, SMEM_TC);
    cudaFuncSetAttribute(gemm_f8h<1>, cudaFuncAttributeMaxDynamicSharedMemorySize, SMEM_TC);
    cudaFuncSetAttribute(gemm_f8h<2>, cudaFuncAttributeMaxDynamicSharedMemorySize, SMEM_TC);

    // 0) weights -> bf16 (+ wp fp8 x64, concat bias)
    cvt_w_kernel<<<dim3(CC / 256, 4), 256>>>(wq, wk, wv, wp, bq, bk, w, w8, bqk);

    // 1) GroupNorm -> bf16 [c, hw]
    groupnorm_kernel<<<BATCH * NGRP, 256>>>(x, gs, gb, xn);

    // 2) transpose xn -> xnT [hw, c]
    transpose_h16<<<dim3(HW / 64, CH / 64, BATCH), 256>>>(
        (const uint16_t*)xn, (uint16_t*)xnT, CH, HW);

    // 3) merged QK (N=1024), split fp8 outputs q[hw,512], k[hw,512]
    dim3 gQK(1024 / 128, HW / 128, BATCH);
    gemm_tc<3><<<gQK, 256, SMEM_TC>>>(xnT, w, q, k, nullptr, bqk,
                                      HW, 1024, CH, 1.f, CHW, 0, CHW);

    // 4) V -> fp8 [c, hw]
    dim3 gV(HW / 128, CH / 128, BATCH);
    gemm_tc<2><<<gV, 256, SMEM_TC>>>(w + 2 * CC, xnT, v, nullptr, bv, nullptr,
                                     CH, HW, CH, 1.f, 0, CHW, CHW);

    // 5) scores + exp fused -> fp8 p, partial row sums
    const float sc = 1.4426950408f / sqrtf((float)CH);
    dim3 gS(HW / 128, HW / 128, BATCH);
    gemm_f8h<0><<<gS, 128, SMEM_TC>>>(q, k, at, ps, nullptr, nullptr,
                                      HW, HW, CH, sc, 0.f, CHW, CHW, SHW);

    // 6) reduce partials -> rsum
    rsum_kernel<<<BATCH * HW / 256, 256>>>(ps, rsum);

    // 7) o28[hw, c] = (p @ v^T) * 256 / rsum   (fp8 out)
    dim3 gO(CH / 128, HW / 128, BATCH);
    gemm_f8h<1><<<gO, 128, SMEM_TC>>>(at, v, o28, nullptr, rsum, nullptr,
                                      HW, CH, HW, 0.f, 0.f, SHW, CHW, CHW);

    // 8) proj fp8: out = (wp8 @ o28^T)/16384 + bp + 64
    dim3 gP(HW / 128, CH / 128, BATCH);
    gemm_f8h<2><<<gP, 128, SMEM_TC>>>(w8, o28, out, nullptr, nullptr, bp,
                                      CH, HW, CH, 1.f / 16384.f, 64.f, 0, CHW, CHW);
}